// round 9
// baseline (speedup 1.0000x reference)
#include <cuda_runtime.h>
#include <math.h>

// ---------------------------------------------------------------------------
// RDHAgent forward. R9: R8 + packed fma.rn.f32x2 GEMM (2 MAC per fma-pipe
// slot; column-paired 64-bit accumulators; Mred loads arrive pre-packed).
// ---------------------------------------------------------------------------

#define NBA   384
#define KNET  650
#define KPAD  672
#define GPITCH 676

__device__ float g_Mred[3 * KPAD * 64];

__device__ __forceinline__ long long bcast2(float v){
    long long r;
    asm("mov.b64 %0, {%1, %1};" : "=l"(r) : "f"(v));
    return r;
}
__device__ __forceinline__ void ffma2(long long &d, long long a, long long b){
    asm("fma.rn.f32x2 %0, %1, %2, %3;" : "=l"(d) : "l"(a), "l"(b), "l"(d));
}

// ---------------- K0: build Mred[net][K][dh] ----------------
__global__ void k_mred(const float* __restrict__ wA2, const float* __restrict__ bA2,
                       const float* __restrict__ wE2, const float* __restrict__ bE2,
                       const float* __restrict__ wL2, const float* __restrict__ bL2,
                       const float* __restrict__ mergw) {
    int K = blockIdx.x, net = blockIdx.y, dh = threadIdx.x;
    float outv = 0.f;
    if (K < KNET) {
        float m0 = mergw[dh], m1 = mergw[64+dh], m2 = mergw[128+dh], m3 = mergw[192+dh];
        float mx = fmaxf(fmaxf(m0,m1), fmaxf(m2,m3));
        float e0 = expf(m0-mx), e1 = expf(m1-mx), e2 = expf(m2-mx), e3 = expf(m3-mx);
        float inv = 1.f/(e0+e1+e2+e3);
        int j10 = K/10;
        int k   = K - j10*10;
        const float* w2 = (net==0)?wA2:((net==1)?wE2:wL2);
        const float* b2 = (net==0)?bA2:((net==1)?bE2:bL2);
        const float* src = (j10 < 64) ? (w2 + j10*2560) : b2;
        int base = k*256 + dh;
        outv = (e0*src[base] + e1*src[base+64] + e2*src[base+128] + e3*src[base+192]) * inv;
    }
    g_Mred[(net*KPAD + K)*64 + dh] = outv;
}

// ---------------- K1: fused ----------------
__global__ void __launch_bounds__(384, 1) k_fused(
    const float* __restrict__ obs, const float* __restrict__ acts,
    const float* __restrict__ wA1, const float* __restrict__ bA1,
    const float* __restrict__ wE1, const float* __restrict__ bE1,
    const float* __restrict__ wL1, const float* __restrict__ bL1,
    const float* __restrict__ fc1w, const float* __restrict__ fc1b,
    const float* __restrict__ fc2w, const float* __restrict__ fc2b,
    float* __restrict__ out)
{
    extern __shared__ float sm[];
    float* Gs    = sm;                       // 3*24*676 = 48672
    float* sW1   = sm + 48672;               // 1728
    float* sB1   = sm + 50400;               // 192
    float* sFeat = sm + 50592;               // 1920
    float* sS    = sm + 52512;
    float* s_velx = sS;        // [24]
    float* s_vely = sS + 24;
    float* s_sint = sS + 48;
    float* s_cost = sS + 72;
    float* s_sina = sS + 96;
    float* s_cosa = sS + 120;
    float* s_rbf  = sS + 144;  // [24][3]
    float* s_act  = sS + 216;  // [3][3]
    float* s_q    = sS + 228;  // [24]

    const int t   = threadIdx.x;
    const int g   = t >> 7;            // net group 0..2
    const int tg  = t & 127;
    const int ba0 = blockIdx.x * 3;

    // ---- stage W1/b1 ----
    for (int idx = t; idx < 576; idx += 384) {
        sW1[idx] = wA1[idx]; sW1[576+idx] = wE1[idx]; sW1[1152+idx] = wL1[idx];
    }
    if (t < 192) {
        int n = t >> 6, c = t & 63;
        sB1[n*64+c] = (n==0)?bA1[c]:((n==1)?bE1[c]:bL1[c]);
    }

    // ---- per-entity scalars ----
    if (t < 24) {
        int bl = t >> 3, j = t & 7;
        const float* ob = obs + (ba0 + bl)*30;
        float px,py,vx,vy;
        if (j < 2)      { px=ob[10+2*j];     py=ob[11+2*j];     vx=ob[20+2*j];     vy=ob[21+2*j]; }
        else if (j < 5) { px=ob[14+2*(j-2)]; py=ob[15+2*(j-2)]; vx=ob[24+2*(j-2)]; vy=ob[25+2*(j-2)]; }
        else            { px=ob[4+2*(j-5)];  py=ob[5+2*(j-5)];  vx=-ob[0];         vy=-ob[1]; }
        float dist = sqrtf(px*px+py*py);
        float id = 1.f/(dist+1e-7f);
        s_sint[t]=py*id; s_cost[t]=px*id;
        float vn = sqrtf(vx*vx+vy*vy);
        float iv = 1.f/(vn+1e-7f);
        s_sina[t]=vy*iv; s_cosa[t]=vx*iv;
        s_velx[t]=vx; s_vely[t]=vy;
        s_rbf[t*3+0]=expf(-0.02f*dist*dist);
        float d1=dist-5.f;  s_rbf[t*3+1]=expf(-0.02f*d1*d1);
        float d2=dist-10.f; s_rbf[t*3+2]=expf(-0.02f*d2*d2);
    } else if (t < 27) {
        int bl = t - 24;
        float ax = acts[(ba0+bl)*2], ay = acts[(ba0+bl)*2+1];
        float an = sqrtf(ax*ax+ay*ay);
        s_act[bl*3+0]=an; s_act[bl*3+1]=ay/(an+1e-7f); s_act[bl*3+2]=ax/(an+1e-7f);
    }
    __syncthreads();

    // ---- feat'[10] per (bl,i,j) ----
    if (t < 192) {
        int bl = t >> 6, i = (t >> 3) & 7, j = t & 7;
        int oI = bl*8 + i, oJ = bl*8 + j;
        float* fd = sFeat + t*10;
        fd[0] = s_rbf[oJ*3+0];
        fd[1] = s_rbf[oJ*3+1];
        fd[2] = s_rbf[oJ*3+2];
        float si=s_sint[oI], ci=s_cost[oI], sj=s_sint[oJ], cj=s_cost[oJ];
        float sa=s_sina[oJ], ca=s_cosa[oJ];
        fd[3] = sj*ci - cj*si;
        fd[4] = cj*ci + sj*si;
        fd[5] = sa*ci - ca*si;
        fd[6] = ca*ci + sa*si;
        fd[7] = s_velx[oJ]-s_velx[oI];
        fd[8] = s_vely[oJ]-s_vely[oI];
        fd[9] = 1.f;
    }
    __syncthreads();

    // ---- build Gs for net g : 4 warps x 6 rows ----
    {
        const int wg = tg >> 5, l = tg & 31;
        const float* w1 = sW1 + g*576;
        const float* b1 = sB1 + g*64;
        float* Gn = Gs + g*24*GPITCH;
        const int jb = (g==0)?0:((g==1)?2:5);
        const int je = (g==0)?2:((g==1)?5:8);
        #pragma unroll
        for (int rr = 0; rr < 6; rr++) {
            int r  = wg*6 + rr;
            int bl = r >> 3, i = r & 7;
            float acc0[10], acc1[10], accb[10];
            #pragma unroll
            for (int k=0;k<10;k++){ acc0[k]=0.f; acc1[k]=0.f; accb[k]=0.f; }
            for (int j = jb; j < je; j++) {
                const float* f = sFeat + (bl*64 + i*8 + j)*10;
                float fr[10];
                #pragma unroll
                for (int k=0;k<10;k++) fr[k]=f[k];
                float h0 = b1[2*l], h1 = b1[2*l+1];
                #pragma unroll
                for (int k=0;k<9;k++){
                    h0 = fmaf(fr[k], w1[k*64+2*l],   h0);
                    h1 = fmaf(fr[k], w1[k*64+2*l+1], h1);
                }
                h0 = (h0>0.f)? h0 : 0.01f*h0;
                h1 = (h1>0.f)? h1 : 0.01f*h1;
                #pragma unroll
                for (int k=0;k<10;k++){
                    acc0[k] = fmaf(h0, fr[k], acc0[k]);
                    acc1[k] = fmaf(h1, fr[k], acc1[k]);
                    accb[k] += fr[k];
                }
            }
            float* gr = Gn + r*GPITCH;
            #pragma unroll
            for (int k=0;k<10;k++){
                gr[(2*l)*10 + k]   = acc0[k];
                gr[(2*l+1)*10 + k] = acc1[k];
            }
            if (l == 0){
                #pragma unroll
                for (int k=0;k<10;k++) gr[640+k] = accb[k];
            }
        }
    }
    // zero pad K=650..675
    for (int idx = t; idx < 3*24*26; idx += 384) {
        int n = idx / (24*26), rem = idx - n*(24*26);
        int r = rem / 26, c = 650 + rem % 26;
        Gs[(n*24 + r)*GPITCH + c] = 0.f;
    }
    __syncthreads();

    // ---- GEMM: per net 24x64x672, thread tile 12x8, K-split 8,
    //      packed f32x2 accumulators (col pairs), M double-buffered ----
    const int ks = tg >> 4;           // 0..7, k range [84ks, 84ks+84)
    const int rg = (tg >> 3) & 1;     // rows 12rg..12rg+11
    const int cg = tg & 7;            // cols 8cg..8cg+7
    const int k0 = ks * 84;

    long long acc[12][4];
    #pragma unroll
    for (int a=0;a<12;a++)
        #pragma unroll
        for (int b=0;b<4;b++) acc[a][b]=0LL;
    {
        const float* Gbase = Gs + (g*24 + rg*12)*GPITCH;
        const float* Mbase = g_Mred + g*KPAD*64 + cg*8;

        // current M buffer: k-even (cA0: cols0-3, cA1: cols4-7), k-odd (cB0,cB1)
        longlong2 cA0 = *(const longlong2*)(Mbase + k0*64);
        longlong2 cA1 = *(const longlong2*)(Mbase + k0*64 + 4);
        longlong2 cB0 = *(const longlong2*)(Mbase + k0*64 + 64);
        longlong2 cB1 = *(const longlong2*)(Mbase + k0*64 + 68);

        for (int kc = k0; kc < k0+84; kc += 2){
            int kn = (kc + 2 < k0+84) ? kc + 2 : kc;
            longlong2 nA0 = *(const longlong2*)(Mbase + kn*64);
            longlong2 nA1 = *(const longlong2*)(Mbase + kn*64 + 4);
            longlong2 nB0 = *(const longlong2*)(Mbase + kn*64 + 64);
            longlong2 nB1 = *(const longlong2*)(Mbase + kn*64 + 68);

            float2 gv[12];
            #pragma unroll
            for (int r=0;r<12;r++)
                gv[r] = *(const float2*)(Gbase + r*GPITCH + kc);

            #pragma unroll
            for (int r=0;r<12;r++){
                long long gx = bcast2(gv[r].x);
                long long gy = bcast2(gv[r].y);
                ffma2(acc[r][0], gx, cA0.x);
                ffma2(acc[r][1], gx, cA0.y);
                ffma2(acc[r][2], gx, cA1.x);
                ffma2(acc[r][3], gx, cA1.y);
                ffma2(acc[r][0], gy, cB0.x);
                ffma2(acc[r][1], gy, cB0.y);
                ffma2(acc[r][2], gy, cB1.x);
                ffma2(acc[r][3], gy, cB1.y);
            }
            cA0 = nA0; cA1 = nA1; cB0 = nB0; cB1 = nB1;
        }
    }
    __syncthreads();   // all Gs reads done before reuse

    // ---- write partials: slab = g*8+ks -> sP[24][24][64] ----
    float* sP = Gs;
    {
        float* base = sP + (g*8 + ks)*1536 + (rg*12)*64 + cg*8;
        #pragma unroll
        for (int r=0;r<12;r++){
            longlong2 o0; o0.x=acc[r][0]; o0.y=acc[r][1];
            longlong2 o1; o1.x=acc[r][2]; o1.y=acc[r][3];
            *(longlong2*)(base + r*64)     = o0;   // cols 0-3 (lo=even col)
            *(longlong2*)(base + r*64 + 4) = o1;   // cols 4-7
        }
    }
    __syncthreads();

    float* sX = Gs + 36864;          // [24][68]
    {
        const float4* p4 = (const float4*)sP;
        float4 v; v.x=0.f; v.y=0.f; v.z=0.f; v.w=0.f;
        #pragma unroll
        for (int s=0;s<24;s++){
            float4 a = p4[s*384 + t];
            v.x += a.x; v.y += a.y; v.z += a.z; v.w += a.w;
        }
        int r = (t*4) >> 6, c = (t*4) & 63;
        float4 o;
        o.x = fmaxf(v.x, 0.f); o.y = fmaxf(v.y, 0.f);
        o.z = fmaxf(v.z, 0.f); o.w = fmaxf(v.w, 0.f);
        *(float4*)(sX + r*68 + c) = o;
    }
    if (t < 72) {
        int r = t / 3, cc = t % 3;
        int bl = r >> 3, i = r & 7;
        float v;
        if (cc == 0) v = s_act[bl*3+0];
        else {
            float sb = s_act[bl*3+1], cb = s_act[bl*3+2];
            float si = s_sint[bl*8+i], ci = s_cost[bl*8+i];
            v = (cc == 1) ? (sb*ci - cb*si) : (cb*ci + sb*si);
        }
        sX[r*68 + 64 + cc] = fmaxf(v, 0.f);
    }
    float* sF = Gs + 38496;          // fc1w [67][64]
    for (int idx = t; idx < 4288; idx += 384) sF[idx] = fc1w[idx];
    __syncthreads();

    // ---- fc1 + fc2 : 12 warps, warp w -> rows 2w, 2w+1 ----
    const int w = t >> 5, l = t & 31;
    float fb0 = fc1b[l], fb1 = fc1b[l+32];
    float w20 = fc2w[l], w21 = fc2w[l+32];
    #pragma unroll
    for (int rr = 0; rr < 2; rr++) {
        int r = w*2 + rr;
        const float* xr = sX + r*68;
        float v0 = fb0, v1 = fb1;
        #pragma unroll
        for (int c = 0; c < 67; c++) {
            float xv = xr[c];
            v0 = fmaf(xv, sF[c*64 + l],      v0);
            v1 = fmaf(xv, sF[c*64 + l + 32], v1);
        }
        v0 = fmaxf(v0, 0.f);
        v1 = fmaxf(v1, 0.f);
        int rowg = ba0*8 + r;
        out[NBA + rowg*64 + l]      = v0;
        out[NBA + rowg*64 + l + 32] = v1;
        float qp = v0*w20 + v1*w21;
        #pragma unroll
        for (int off=16; off; off>>=1) qp += __shfl_down_sync(0xffffffffu, qp, off);
        if (l == 0) s_q[r] = qp;
    }
    __syncthreads();
    if (t < 3) {
        float s = 0.f;
        #pragma unroll
        for (int k=0;k<8;k++) s += s_q[t*8+k];
        out[ba0 + t] = s*0.125f + fc2b[0];
    }
}

// ---------------- launch ----------------
extern "C" void kernel_launch(void* const* d_in, const int* in_sizes, int n_in,
                              void* d_out, int out_size) {
    const float* inputs = (const float*)d_in[0];
    const float* actions = (const float*)d_in[2];
    const float* hA1w=(const float*)d_in[3],  *hA1b=(const float*)d_in[4];
    const float* hA2w=(const float*)d_in[5],  *hA2b=(const float*)d_in[6];
    const float* hE1w=(const float*)d_in[7],  *hE1b=(const float*)d_in[8];
    const float* hE2w=(const float*)d_in[9],  *hE2b=(const float*)d_in[10];
    const float* hL1w=(const float*)d_in[11], *hL1b=(const float*)d_in[12];
    const float* hL2w=(const float*)d_in[13], *hL2b=(const float*)d_in[14];
    const float* mergw=(const float*)d_in[15];
    const float* fc1w=(const float*)d_in[16], *fc1b=(const float*)d_in[17];
    const float* fc2w=(const float*)d_in[18], *fc2b=(const float*)d_in[19];
    float* out = (float*)d_out;

    const int smem_bytes = 52764 * 4;   // 211056 B
    cudaFuncSetAttribute(k_fused, cudaFuncAttributeMaxDynamicSharedMemorySize, smem_bytes);

    dim3 g0(KPAD, 3);
    k_mred<<<g0, 64>>>(hA2w,hA2b,hE2w,hE2b,hL2w,hL2b,mergw);
    k_fused<<<128, 384, smem_bytes>>>(inputs, actions,
                                      hA1w,hA1b,hE1w,hE1b,hL1w,hL1b,
                                      fc1w,fc1b,fc2w,fc2b, out);
}

// round 10
// speedup vs baseline: 1.1795x; 1.1795x over previous
#include <cuda_runtime.h>
#include <math.h>
#include <stdint.h>

// ---------------------------------------------------------------------------
// RDHAgent forward. R10: GEMM moved to tensor pipe via legacy tf32
// mma.sync.aligned.m16n8k8 (rel-err budget 1e-3; tf32 gives ~1e-4).
// 12 warps = 3 nets x 4 col-groups; warp does 2 m-tiles x 2 n-tiles, K=672.
// ---------------------------------------------------------------------------

#define NBA   384
#define KNET  650
#define KPAD  672
#define GPITCH 676

__device__ float g_Mred[3 * KPAD * 64];

__device__ __forceinline__ uint32_t cvt_tf32(float x){
    uint32_t r; asm("cvt.rna.tf32.f32 %0, %1;" : "=r"(r) : "f"(x)); return r;
}
__device__ __forceinline__ void mma_tf32(float* d, const uint32_t* a, uint32_t b0, uint32_t b1){
    asm("mma.sync.aligned.m16n8k8.row.col.f32.tf32.tf32.f32 "
        "{%0,%1,%2,%3},{%4,%5,%6,%7},{%8,%9},{%0,%1,%2,%3};"
        : "+f"(d[0]),"+f"(d[1]),"+f"(d[2]),"+f"(d[3])
        : "r"(a[0]),"r"(a[1]),"r"(a[2]),"r"(a[3]), "r"(b0),"r"(b1));
}

// ---------------- K0: build Mred[net][K][dh] ----------------
__global__ void k_mred(const float* __restrict__ wA2, const float* __restrict__ bA2,
                       const float* __restrict__ wE2, const float* __restrict__ bE2,
                       const float* __restrict__ wL2, const float* __restrict__ bL2,
                       const float* __restrict__ mergw) {
    int K = blockIdx.x, net = blockIdx.y, dh = threadIdx.x;
    float outv = 0.f;
    if (K < KNET) {
        float m0 = mergw[dh], m1 = mergw[64+dh], m2 = mergw[128+dh], m3 = mergw[192+dh];
        float mx = fmaxf(fmaxf(m0,m1), fmaxf(m2,m3));
        float e0 = expf(m0-mx), e1 = expf(m1-mx), e2 = expf(m2-mx), e3 = expf(m3-mx);
        float inv = 1.f/(e0+e1+e2+e3);
        int j10 = K/10;
        int k   = K - j10*10;
        const float* w2 = (net==0)?wA2:((net==1)?wE2:wL2);
        const float* b2 = (net==0)?bA2:((net==1)?bE2:bL2);
        const float* src = (j10 < 64) ? (w2 + j10*2560) : b2;
        int base = k*256 + dh;
        outv = (e0*src[base] + e1*src[base+64] + e2*src[base+128] + e3*src[base+192]) * inv;
    }
    g_Mred[(net*KPAD + K)*64 + dh] = outv;
}

// ---------------- K1: fused ----------------
__global__ void __launch_bounds__(384, 1) k_fused(
    const float* __restrict__ obs, const float* __restrict__ acts,
    const float* __restrict__ wA1, const float* __restrict__ bA1,
    const float* __restrict__ wE1, const float* __restrict__ bE1,
    const float* __restrict__ wL1, const float* __restrict__ bL1,
    const float* __restrict__ fc1w, const float* __restrict__ fc1b,
    const float* __restrict__ fc2w, const float* __restrict__ fc2b,
    float* __restrict__ out)
{
    extern __shared__ float sm[];
    float* Gs    = sm;                       // 3*24*676 = 48672
    float* sW1   = sm + 48672;               // 1728
    float* sB1   = sm + 50400;               // 192
    float* sFeat = sm + 50592;               // 1920
    float* sS    = sm + 52512;
    float* s_velx = sS;        // [24]
    float* s_vely = sS + 24;
    float* s_sint = sS + 48;
    float* s_cost = sS + 72;
    float* s_sina = sS + 96;
    float* s_cosa = sS + 120;
    float* s_rbf  = sS + 144;  // [24][3]
    float* s_act  = sS + 216;  // [3][3]
    float* s_q    = sS + 228;  // [24]

    const int t   = threadIdx.x;
    const int g   = t >> 7;            // build-phase net group 0..2
    const int tg  = t & 127;
    const int ba0 = blockIdx.x * 3;

    // ---- stage W1/b1 ----
    for (int idx = t; idx < 576; idx += 384) {
        sW1[idx] = wA1[idx]; sW1[576+idx] = wE1[idx]; sW1[1152+idx] = wL1[idx];
    }
    if (t < 192) {
        int n = t >> 6, c = t & 63;
        sB1[n*64+c] = (n==0)?bA1[c]:((n==1)?bE1[c]:bL1[c]);
    }

    // ---- per-entity scalars ----
    if (t < 24) {
        int bl = t >> 3, j = t & 7;
        const float* ob = obs + (ba0 + bl)*30;
        float px,py,vx,vy;
        if (j < 2)      { px=ob[10+2*j];     py=ob[11+2*j];     vx=ob[20+2*j];     vy=ob[21+2*j]; }
        else if (j < 5) { px=ob[14+2*(j-2)]; py=ob[15+2*(j-2)]; vx=ob[24+2*(j-2)]; vy=ob[25+2*(j-2)]; }
        else            { px=ob[4+2*(j-5)];  py=ob[5+2*(j-5)];  vx=-ob[0];         vy=-ob[1]; }
        float dist = sqrtf(px*px+py*py);
        float id = 1.f/(dist+1e-7f);
        s_sint[t]=py*id; s_cost[t]=px*id;
        float vn = sqrtf(vx*vx+vy*vy);
        float iv = 1.f/(vn+1e-7f);
        s_sina[t]=vy*iv; s_cosa[t]=vx*iv;
        s_velx[t]=vx; s_vely[t]=vy;
        s_rbf[t*3+0]=expf(-0.02f*dist*dist);
        float d1=dist-5.f;  s_rbf[t*3+1]=expf(-0.02f*d1*d1);
        float d2=dist-10.f; s_rbf[t*3+2]=expf(-0.02f*d2*d2);
    } else if (t < 27) {
        int bl = t - 24;
        float ax = acts[(ba0+bl)*2], ay = acts[(ba0+bl)*2+1];
        float an = sqrtf(ax*ax+ay*ay);
        s_act[bl*3+0]=an; s_act[bl*3+1]=ay/(an+1e-7f); s_act[bl*3+2]=ax/(an+1e-7f);
    }
    __syncthreads();

    // ---- feat'[10] per (bl,i,j) ----
    if (t < 192) {
        int bl = t >> 6, i = (t >> 3) & 7, j = t & 7;
        int oI = bl*8 + i, oJ = bl*8 + j;
        float* fd = sFeat + t*10;
        fd[0] = s_rbf[oJ*3+0];
        fd[1] = s_rbf[oJ*3+1];
        fd[2] = s_rbf[oJ*3+2];
        float si=s_sint[oI], ci=s_cost[oI], sj=s_sint[oJ], cj=s_cost[oJ];
        float sa=s_sina[oJ], ca=s_cosa[oJ];
        fd[3] = sj*ci - cj*si;
        fd[4] = cj*ci + sj*si;
        fd[5] = sa*ci - ca*si;
        fd[6] = ca*ci + sa*si;
        fd[7] = s_velx[oJ]-s_velx[oI];
        fd[8] = s_vely[oJ]-s_vely[oI];
        fd[9] = 1.f;
    }
    __syncthreads();

    // ---- build Gs for net g : 4 warps x 6 rows ----
    {
        const int wg = tg >> 5, l = tg & 31;
        const float* w1 = sW1 + g*576;
        const float* b1 = sB1 + g*64;
        float* Gn = Gs + g*24*GPITCH;
        const int jb = (g==0)?0:((g==1)?2:5);
        const int je = (g==0)?2:((g==1)?5:8);
        #pragma unroll
        for (int rr = 0; rr < 6; rr++) {
            int r  = wg*6 + rr;
            int bl = r >> 3, i = r & 7;
            float acc0[10], acc1[10], accb[10];
            #pragma unroll
            for (int k=0;k<10;k++){ acc0[k]=0.f; acc1[k]=0.f; accb[k]=0.f; }
            for (int j = jb; j < je; j++) {
                const float* f = sFeat + (bl*64 + i*8 + j)*10;
                float fr[10];
                #pragma unroll
                for (int k=0;k<10;k++) fr[k]=f[k];
                float h0 = b1[2*l], h1 = b1[2*l+1];
                #pragma unroll
                for (int k=0;k<9;k++){
                    h0 = fmaf(fr[k], w1[k*64+2*l],   h0);
                    h1 = fmaf(fr[k], w1[k*64+2*l+1], h1);
                }
                h0 = (h0>0.f)? h0 : 0.01f*h0;
                h1 = (h1>0.f)? h1 : 0.01f*h1;
                #pragma unroll
                for (int k=0;k<10;k++){
                    acc0[k] = fmaf(h0, fr[k], acc0[k]);
                    acc1[k] = fmaf(h1, fr[k], acc1[k]);
                    accb[k] += fr[k];
                }
            }
            float* gr = Gn + r*GPITCH;
            #pragma unroll
            for (int k=0;k<10;k++){
                gr[(2*l)*10 + k]   = acc0[k];
                gr[(2*l+1)*10 + k] = acc1[k];
            }
            if (l == 0){
                #pragma unroll
                for (int k=0;k<10;k++) gr[640+k] = accb[k];
            }
        }
    }
    // zero pad K=650..675
    for (int idx = t; idx < 3*24*26; idx += 384) {
        int n = idx / (24*26), rem = idx - n*(24*26);
        int r = rem / 26, c = 650 + rem % 26;
        Gs[(n*24 + r)*GPITCH + c] = 0.f;
    }
    __syncthreads();

    // ---- GEMM via tf32 mma.sync: warp -> (net, 16-col group) ----
    const int wI = t >> 5, lane = t & 31;
    const int g2 = wI >> 2;           // net 0..2
    const int nh = wI & 3;            // col group: cols nh*16..nh*16+15
    const int qid = lane >> 2, tid4 = lane & 3;

    float D[2][2][4];
    #pragma unroll
    for (int a=0;a<2;a++)
        #pragma unroll
        for (int b=0;b<2;b++)
            #pragma unroll
            for (int c=0;c<4;c++) D[a][b][c]=0.f;
    {
        const float* Gn = Gs + g2*24*GPITCH;
        const float* gr0 = Gn + qid*GPITCH;        // rows 0..7
        const float* gr1 = Gn + (qid+8)*GPITCH;    // rows 8..15
        const float* gr2 = Gn + (16+qid)*GPITCH;   // rows 16..23
        const float* Mn = g_Mred + g2*KPAD*64;

        #pragma unroll 2
        for (int k = 0; k < KPAD; k += 8) {
            uint32_t a0[4], a1[4];
            a0[0] = cvt_tf32(gr0[k+tid4]);
            a0[1] = cvt_tf32(gr1[k+tid4]);
            a0[2] = cvt_tf32(gr0[k+tid4+4]);
            a0[3] = cvt_tf32(gr1[k+tid4+4]);
            a1[0] = cvt_tf32(gr2[k+tid4]);
            a1[1] = 0u;                      // rows 24..31 are padding
            a1[2] = cvt_tf32(gr2[k+tid4+4]);
            a1[3] = 0u;
            #pragma unroll
            for (int nt=0; nt<2; nt++){
                int c = nh*16 + nt*8 + qid;
                uint32_t b0 = cvt_tf32(Mn[(k+tid4)*64 + c]);
                uint32_t b1 = cvt_tf32(Mn[(k+tid4+4)*64 + c]);
                mma_tf32(D[0][nt], a0, b0, b1);
                mma_tf32(D[1][nt], a1, b0, b1);
            }
        }
    }
    __syncthreads();   // all Gs reads done before reuse

    // ---- write per-net partials: sP[3][24][64] in reused Gs ----
    float* sP = Gs;
    {
        float* base = sP + g2*1536;
        #pragma unroll
        for (int nt=0; nt<2; nt++){
            int c = nh*16 + nt*8 + tid4*2;
            base[ qid     *64 + c]   = D[0][nt][0];
            base[ qid     *64 + c+1] = D[0][nt][1];
            base[(qid+8)  *64 + c]   = D[0][nt][2];
            base[(qid+8)  *64 + c+1] = D[0][nt][3];
            base[(16+qid) *64 + c]   = D[1][nt][0];
            base[(16+qid) *64 + c+1] = D[1][nt][1];
            // D[1][nt][2..3] -> padding rows 24..31, discarded
        }
    }
    __syncthreads();

    float* sX = Gs + 36864;          // [24][68]
    {
        const float4* p4 = (const float4*)sP;
        float4 v;
        float4 x0 = p4[t], x1 = p4[384 + t], x2 = p4[768 + t];
        v.x = x0.x + x1.x + x2.x;
        v.y = x0.y + x1.y + x2.y;
        v.z = x0.z + x1.z + x2.z;
        v.w = x0.w + x1.w + x2.w;
        int r = (t*4) >> 6, c = (t*4) & 63;
        float4 o;
        o.x = fmaxf(v.x, 0.f); o.y = fmaxf(v.y, 0.f);
        o.z = fmaxf(v.z, 0.f); o.w = fmaxf(v.w, 0.f);
        *(float4*)(sX + r*68 + c) = o;
    }
    if (t < 72) {
        int r = t / 3, cc = t % 3;
        int bl = r >> 3, i = r & 7;
        float v;
        if (cc == 0) v = s_act[bl*3+0];
        else {
            float sb = s_act[bl*3+1], cb = s_act[bl*3+2];
            float si = s_sint[bl*8+i], ci = s_cost[bl*8+i];
            v = (cc == 1) ? (sb*ci - cb*si) : (cb*ci + sb*si);
        }
        sX[r*68 + 64 + cc] = fmaxf(v, 0.f);
    }
    float* sF = Gs + 38496;          // fc1w [67][64]
    for (int idx = t; idx < 4288; idx += 384) sF[idx] = fc1w[idx];
    __syncthreads();

    // ---- fc1 + fc2 : 12 warps, warp w -> rows 2w, 2w+1 ----
    const int w = t >> 5, l = t & 31;
    float fb0 = fc1b[l], fb1 = fc1b[l+32];
    float w20 = fc2w[l], w21 = fc2w[l+32];
    #pragma unroll
    for (int rr = 0; rr < 2; rr++) {
        int r = w*2 + rr;
        const float* xr = sX + r*68;
        float v0 = fb0, v1 = fb1;
        #pragma unroll
        for (int c = 0; c < 67; c++) {
            float xv = xr[c];
            v0 = fmaf(xv, sF[c*64 + l],      v0);
            v1 = fmaf(xv, sF[c*64 + l + 32], v1);
        }
        v0 = fmaxf(v0, 0.f);
        v1 = fmaxf(v1, 0.f);
        int rowg = ba0*8 + r;
        out[NBA + rowg*64 + l]      = v0;
        out[NBA + rowg*64 + l + 32] = v1;
        float qp = v0*w20 + v1*w21;
        #pragma unroll
        for (int off=16; off; off>>=1) qp += __shfl_down_sync(0xffffffffu, qp, off);
        if (l == 0) s_q[r] = qp;
    }
    __syncthreads();
    if (t < 3) {
        float s = 0.f;
        #pragma unroll
        for (int k=0;k<8;k++) s += s_q[t*8+k];
        out[ba0 + t] = s*0.125f + fc2b[0];
    }
}

// ---------------- launch ----------------
extern "C" void kernel_launch(void* const* d_in, const int* in_sizes, int n_in,
                              void* d_out, int out_size) {
    const float* inputs = (const float*)d_in[0];
    const float* actions = (const float*)d_in[2];
    const float* hA1w=(const float*)d_in[3],  *hA1b=(const float*)d_in[4];
    const float* hA2w=(const float*)d_in[5],  *hA2b=(const float*)d_in[6];
    const float* hE1w=(const float*)d_in[7],  *hE1b=(const float*)d_in[8];
    const float* hE2w=(const float*)d_in[9],  *hE2b=(const float*)d_in[10];
    const float* hL1w=(const float*)d_in[11], *hL1b=(const float*)d_in[12];
    const float* hL2w=(const float*)d_in[13], *hL2b=(const float*)d_in[14];
    const float* mergw=(const float*)d_in[15];
    const float* fc1w=(const float*)d_in[16], *fc1b=(const float*)d_in[17];
    const float* fc2w=(const float*)d_in[18], *fc2b=(const float*)d_in[19];
    float* out = (float*)d_out;

    const int smem_bytes = 52764 * 4;   // 211056 B
    cudaFuncSetAttribute(k_fused, cudaFuncAttributeMaxDynamicSharedMemorySize, smem_bytes);

    dim3 g0(KPAD, 3);
    k_mred<<<g0, 64>>>(hA2w,hA2b,hE2w,hE2b,hL2w,hL2b,mergw);
    k_fused<<<128, 384, smem_bytes>>>(inputs, actions,
                                      hA1w,hA1b,hE1w,hE1b,hL1w,hL1b,
                                      fc1w,fc1b,fc2w,fc2b, out);
}